// round 15
// baseline (speedup 1.0000x reference)
#include <cuda_runtime.h>
#include <cuda_bf16.h>
#include <stdint.h>

#define T_ 12
#define BN_TOT 131072
#define NPRED (BN_TOT * 12)

__device__ __align__(16) uint32_t g_Bh[T_ * 6144];
__device__ __align__(16) uint32_t g_Bx[T_ * 1536];
__device__ __align__(16) float g_E2[T_ * 128];

struct Meta { const float *wz, *bz, *Wl[6], *bl[6], *Wb[6], *bb[6], *Wo; };

__device__ __forceinline__ float dot32(const float* a, const float* b) {
    float s = 0.f;
#pragma unroll
    for (int m = 0; m < 32; m++) s = fmaf(a[m], b[m], s);
    return s;
}
__device__ __forceinline__ uint32_t pkbf(float a, float b) {
    return ((uint32_t)__bfloat16_as_ushort(__float2bfloat16(b)) << 16) |
           __bfloat16_as_ushort(__float2bfloat16(a));
}
__device__ __forceinline__ uint32_t pk2(float a, float b) {
    uint32_t d;
    asm("cvt.rn.bf16x2.f32 %0, %1, %2;" : "=r"(d) : "f"(b), "f"(a));
    return d;
}
__device__ __forceinline__ float bf16f(float x) {
    return __bfloat162float(__float2bfloat16(x));
}
__device__ __forceinline__ float tanh_ap(float x) {
    float y;
    asm("tanh.approx.f32 %0, %1;" : "=f"(y) : "f"(x));
    return y;
}

// g_Bh: h-weight fragments (bf16, r/z pre-scaled 0.5): word = t*6144 + (g*8+j)*256 + ks*64 + lane*2 + half
// g_Bx: x/bias fragments: word = t*1536 + (g*8+j)*64 + lane (lanes 0..31 used); by lane%4:
//   q0/q2: {wxhi0, wxhi1}   q1: {bias_hi, bias_lo}   q3: {wxlo0, wxlo1}
// g_E2: per (t,i): {bch, Wo}
__global__ void pre_kernel(Meta p) {
    int idx = blockIdx.x * 256 + threadIdx.x;
    if (idx < 73728) {
        int t = idx / 6144, r = idx % 6144;
        int nt = r / 256, r2 = r % 256;
        int ks = r2 / 64, r3 = r2 % 64;
        int ln = r3 >> 1, half = r3 & 1;
        int n = nt * 8 + (ln >> 2);
        int k0 = ks * 16 + (ln & 3) * 2 + half * 8;
        int g = n >> 6, i = n & 63;
        float gs = (g < 2) ? 0.5f : 1.0f;
        const float* wzt = p.wz + t * 32;
        float s0 = gs * (dot32(wzt, p.Wl[2 * g + 1] + (i * 64 + k0) * 32) + p.bl[2 * g + 1][i * 64 + k0]);
        float s1 = gs * (dot32(wzt, p.Wl[2 * g + 1] + (i * 64 + k0 + 1) * 32) + p.bl[2 * g + 1][i * 64 + k0 + 1]);
        g_Bh[idx] = pkbf(s0, s1);
    } else if (idx < 73728 + 18432) {
        int e = idx - 73728;
        int t = e / 1536, r = e % 1536;
        int g = r / 512, r2 = r % 512;
        int j = r2 / 64, ln = r2 % 64;
        uint32_t outw = 0u;
        if (ln < 32) {
            int q = ln & 3, nn = j * 8 + (ln >> 2);
            float gs = (g < 2) ? 0.5f : 1.0f;
            const float* wzt = p.wz + t * 32;
            if (q == 1) {
                float b;
                if (g == 0)
                    b = 0.5f * (dot32(p.bz + t * 32, p.Wb[0] + nn * 32) + p.bb[0][nn]
                              + dot32(p.bz + t * 32, p.Wb[1] + nn * 32) + p.bb[1][nn]);
                else if (g == 1)
                    b = 0.5f * (dot32(p.bz + t * 32, p.Wb[2] + nn * 32) + p.bb[2][nn]
                              + dot32(p.bz + t * 32, p.Wb[3] + nn * 32) + p.bb[3][nn]);
                else
                    b = dot32(p.bz + t * 32, p.Wb[4] + nn * 32) + p.bb[4][nn];
                outw = pkbf(b, b - bf16f(b));
            } else {
                float w0 = gs * (dot32(wzt, p.Wl[2 * g] + (nn * 2 + 0) * 32) + p.bl[2 * g][nn * 2 + 0]);
                float w1 = gs * (dot32(wzt, p.Wl[2 * g] + (nn * 2 + 1) * 32) + p.bl[2 * g][nn * 2 + 1]);
                if (q == 3) outw = pkbf(w0 - bf16f(w0), w1 - bf16f(w1));
                else        outw = pkbf(w0, w1);
            }
        }
        g_Bx[e] = outw;
    } else if (idx < 73728 + 18432 + 768) {
        int e = idx - 73728 - 18432;
        int t = e / 64, i = e % 64;
        g_E2[t * 128 + i * 2]     = dot32(p.bz + t * 32, p.Wb[5] + i * 32) + p.bb[5][i];
        g_E2[t * 128 + i * 2 + 1] = p.Wo[i];
    }
}

#define MMA(d, a0_, a1_, a2_, a3_, b0_, b1_) \
    asm volatile("mma.sync.aligned.m16n8k16.row.col.f32.bf16.bf16.f32 " \
        "{%0,%1,%2,%3}, {%4,%5,%6,%7}, {%8,%9}, {%0,%1,%2,%3};" \
        : "+f"((d)[0]), "+f"((d)[1]), "+f"((d)[2]), "+f"((d)[3]) \
        : "r"(a0_), "r"(a1_), "r"(a2_), "r"(a3_), "r"(b0_), "r"(b1_))

#define HF_STRIDE 132          // floats per element row; bank-conflict-free (132%32=4)
#define SM_BH0 0
#define SM_BH1 24576
#define SM_BX0 49152
#define SM_BX1 55296
#define SM_X   61440
#define SM_SEQ 74240
#define SM_E20 80384
#define SM_E21 80896
#define SM_WP  81408
#define SM_BP  81984
#define SM_HF  82048
#define SMEM_BYTES (82048 + 64 * HF_STRIDE * 4)   // 82048 + 33792 = 115840

// 256 threads, 8 warps, 16 rows/warp. sHf[e*HF_STRIDE + row] fp32 master h.
__global__ void __launch_bounds__(256, 2)
gru_mma(const float* __restrict__ x, const float* __restrict__ bo,
        const float* __restrict__ Wp, const float* __restrict__ bp,
        float* __restrict__ out, int dup)
{
    extern __shared__ char smem[];
    const int tid = threadIdx.x, lane = tid & 31, wid = tid >> 5;
    const int bn0 = blockIdx.x * 128;
    const int g4 = lane >> 2, q = lane & 3, q2 = q * 2;
    const int r0 = wid * 16 + g4;           // local rows r0, r0+8

    float* sx = (float*)(smem + SM_X);
    float* sSeq = (float*)(smem + SM_SEQ);
    float* sHf = (float*)(smem + SM_HF);
    if (tid < 12) ((float*)(smem + SM_BP))[tid] = bp[tid];
    if (tid < 144) ((float*)(smem + SM_WP))[tid] = Wp[tid];
    if (tid < 128) {
        const float4* gx = (const float4*)x + (size_t)(bn0 + tid) * 6;
#pragma unroll
        for (int u = 0; u < 6; u++) {
            float4 v = gx[u];
            sx[tid * 25 + 4 * u] = v.x; sx[tid * 25 + 4 * u + 1] = v.y;
            sx[tid * 25 + 4 * u + 2] = v.z; sx[tid * 25 + 4 * u + 3] = v.w;
        }
    }
    for (int k = tid; k < 64 * HF_STRIDE; k += 256) sHf[k] = 0.f;
    {   // prologue: stage t=0 into buffer 0
        const uint4* gb = (const uint4*)(g_Bh);
        uint4* db = (uint4*)(smem + SM_BH0);
#pragma unroll
        for (int k = 0; k < 6; k++) db[k * 256 + tid] = gb[k * 256 + tid];
        if (tid < 128) {
            const uint4* gbx = (const uint4*)(g_Bx);
            uint4* dbx = (uint4*)(smem + SM_BX0);
#pragma unroll
            for (int k = 0; k < 3; k++) dbx[k * 128 + tid] = gbx[k * 128 + tid];
        }
        if (tid < 32) ((uint4*)(smem + SM_E20))[tid] = ((const uint4*)g_E2)[tid];
    }

    uint32_t Ah[4][4];
#pragma unroll
    for (int b = 0; b < 4; b++)
#pragma unroll
        for (int c = 0; c < 4; c++) Ah[b][c] = 0u;
    const float bo0 = __ldg(bo);
    __syncthreads();

    for (int t = 0; t < T_; t++) {
        const uint32_t* sBh = (const uint32_t*)(smem + ((t & 1) ? SM_BH1 : SM_BH0));
        const uint32_t* sBx = (const uint32_t*)(smem + ((t & 1) ? SM_BX1 : SM_BX0));
        const float4* sE2 = (const float4*)(smem + ((t & 1) ? SM_E21 : SM_E20));

        // stage next step into the other buffer
        if (t + 1 < T_) {
            const uint4* gb = (const uint4*)(g_Bh + (t + 1) * 6144);
            uint4* db = (uint4*)(smem + (((t + 1) & 1) ? SM_BH1 : SM_BH0));
#pragma unroll
            for (int k = 0; k < 6; k++) db[k * 256 + tid] = gb[k * 256 + tid];
            if (tid < 128) {
                const uint4* gbx = (const uint4*)(g_Bx + (t + 1) * 1536);
                uint4* dbx = (uint4*)(smem + (((t + 1) & 1) ? SM_BX1 : SM_BX0));
#pragma unroll
                for (int k = 0; k < 3; k++) dbx[k * 128 + tid] = gbx[k * 128 + tid];
            }
            if (tid < 32)
                ((uint4*)(smem + (((t + 1) & 1) ? SM_E21 : SM_E20)))[tid] =
                    ((const uint4*)(g_E2 + (t + 1) * 128))[tid];
        }

        float oacc[2] = {0.f, 0.f};
        uint32_t ax0, ax1;
        {   // x/bias A fragments for rows r0, r0+8: [xhi, 1/1, xlo, xhi] by quad pos
            float xa0 = sx[r0 * 25 + 2 * t],       xa1 = sx[r0 * 25 + 2 * t + 1];
            float xb0 = sx[(r0 + 8) * 25 + 2 * t], xb1 = sx[(r0 + 8) * 25 + 2 * t + 1];
            if (q == 1) { ax0 = 0x3F803F80u; ax1 = 0x3F803F80u; }
            else if (q == 2) {
                ax0 = pk2(xa0 - bf16f(xa0), xa1 - bf16f(xa1));
                ax1 = pk2(xb0 - bf16f(xb0), xb1 - bf16f(xb1));
            } else {
                ax0 = pk2(bf16f(xa0), bf16f(xa1));
                ax1 = pk2(bf16f(xb0), bf16f(xb1));
            }
        }

#pragma unroll
        for (int j = 0; j < 8; j++) {
            float d[3][4], dxc[4];
#pragma unroll
            for (int a = 0; a < 3; a++)
#pragma unroll
                for (int c = 0; c < 4; c++) d[a][c] = 0.f;
#pragma unroll
            for (int c = 0; c < 4; c++) dxc[c] = 0.f;
#pragma unroll
            for (int ks = 0; ks < 4; ks++) {
#pragma unroll
                for (int g3 = 0; g3 < 3; g3++) {
                    int bi = ((g3 * 8 + j) * 4 + ks) * 64 + lane * 2;
                    uint2 bh = *(const uint2*)(sBh + bi);
                    MMA(d[g3], Ah[ks][0], Ah[ks][1], Ah[ks][2], Ah[ks][3], bh.x, bh.y);
                }
            }
            {   // x-part + bias MMAs
                uint32_t bxr = sBx[(0 * 8 + j) * 64 + lane];
                uint32_t bxz = sBx[(1 * 8 + j) * 64 + lane];
                uint32_t bxc = sBx[(2 * 8 + j) * 64 + lane];
                MMA(d[0], ax0, ax1, 0u, 0u, bxr, 0u);
                MMA(d[1], ax0, ax1, 0u, 0u, bxz, 0u);
                MMA(dxc, ax0, ax1, 0u, 0u, bxc, 0u);
            }
            int i0 = j * 8 + q2;
            float4 e4 = sE2[i0 >> 1];   // {bch(i0), wo(i0), bch(i0+1), wo(i0+1)}
#pragma unroll
            for (int pp = 0; pp < 2; pp++) {
                int row = r0 + pp * 8;
                float hold0 = sHf[i0 * HF_STRIDE + row];
                float hold1 = sHf[(i0 + 1) * HF_STRIDE + row];

                float tr0 = tanh_ap(d[0][pp * 2]);
                float tz0 = tanh_ap(d[1][pp * 2]);
                float u0 = d[2][pp * 2] + e4.x;
                float c0 = tanh_ap(fmaf(0.5f, fmaf(tr0, u0, u0), dxc[pp * 2]));
                float hn0 = 0.5f * fmaf(tz0, hold0 - c0, hold0 + c0);

                float tr1 = tanh_ap(d[0][pp * 2 + 1]);
                float tz1 = tanh_ap(d[1][pp * 2 + 1]);
                float u1 = d[2][pp * 2 + 1] + e4.z;
                float c1 = tanh_ap(fmaf(0.5f, fmaf(tr1, u1, u1), dxc[pp * 2 + 1]));
                float hn1 = 0.5f * fmaf(tz1, hold1 - c1, hold1 + c1);

                oacc[pp] = fmaf(hn0, e4.y, oacc[pp]);
                oacc[pp] = fmaf(hn1, e4.w, oacc[pp]);
                sHf[i0 * HF_STRIDE + row] = hn0;
                sHf[(i0 + 1) * HF_STRIDE + row] = hn1;
            }
        }
        __syncwarp();   // epilogue writes (all lanes) visible before rebuild reads
        // rebuild A fragments: Ah[ks][c] = h[row(c)][k(c)] pairs, bf16-packed
#pragma unroll
        for (int ks = 0; ks < 4; ks++) {
            int e = ks * 16 + q2;
#pragma unroll
            for (int c = 0; c < 4; c++) {
                int ee = e + (c >> 1) * 8;          // c=2,3 -> k+8
                int row = r0 + (c & 1) * 8;         // c odd -> row+8
                Ah[ks][c] = pk2(sHf[ee * HF_STRIDE + row],
                                sHf[(ee + 1) * HF_STRIDE + row]);
            }
        }
#pragma unroll
        for (int pp = 0; pp < 2; pp++) {
            float v = oacc[pp];
            v += __shfl_xor_sync(0xffffffffu, v, 1);
            v += __shfl_xor_sync(0xffffffffu, v, 2);
            v = fmaxf(v + bo0, 0.f);
            sSeq[t * 128 + r0 + pp * 8] = v;        // quad lanes write same value
        }
        __syncthreads();   // staging of t+1 done + buf[t&1] reads done
    }

    if (tid < 128) {
        const float* sWp = (const float*)(smem + SM_WP);
        const float* sbp = (const float*)(smem + SM_BP);
        float sq[12];
#pragma unroll
        for (int tt = 0; tt < 12; tt++) sq[tt] = sSeq[tt * 128 + tid];
        float pr[12];
#pragma unroll
        for (int p = 0; p < 12; p++) {
            float a = sbp[p];
#pragma unroll
            for (int tt = 0; tt < 12; tt++) a = fmaf(sq[tt], sWp[p * 12 + tt], a);
            pr[p] = a;
        }
        size_t base = (size_t)(bn0 + tid) * 12;
        float4* o4 = (float4*)(out + base);
        o4[0] = make_float4(pr[0], pr[1], pr[2], pr[3]);
        o4[1] = make_float4(pr[4], pr[5], pr[6], pr[7]);
        o4[2] = make_float4(pr[8], pr[9], pr[10], pr[11]);
        if (dup) {
            float4* d4 = (float4*)(out + NPRED + base);
            d4[0] = make_float4(pr[0], pr[1], pr[2], pr[3]);
            d4[1] = make_float4(pr[4], pr[5], pr[6], pr[7]);
            d4[2] = make_float4(pr[8], pr[9], pr[10], pr[11]);
        }
    }
}

extern "C" void kernel_launch(void* const* d_in, const int* in_sizes, int n_in,
                              void* d_out, int out_size) {
    Meta m;
    m.wz = (const float*)d_in[2];
    m.bz = (const float*)d_in[3];
    for (int g = 0; g < 6; g++) {   // rx, rh, zx, zh, cx, ch
        m.Wl[g] = (const float*)d_in[4 + g * 4];
        m.bl[g] = (const float*)d_in[5 + g * 4];
        m.Wb[g] = (const float*)d_in[6 + g * 4];
        m.bb[g] = (const float*)d_in[7 + g * 4];
    }
    m.Wo = (const float*)d_in[28];
    const float* x  = (const float*)d_in[0];
    const float* bo = (const float*)d_in[29];
    const float* Wp = (const float*)d_in[30];
    const float* bp = (const float*)d_in[31];
    float* out = (float*)d_out;

    pre_kernel<<<364, 256>>>(m);

    int dup = (out_size >= 2 * NPRED) ? 1 : 0;
    cudaFuncSetAttribute(gru_mma, cudaFuncAttributeMaxDynamicSharedMemorySize, SMEM_BYTES);
    gru_mma<<<1024, 256, SMEM_BYTES>>>(x, bo, Wp, bp, out, dup);
}

// round 16
// speedup vs baseline: 1.1731x; 1.1731x over previous
#include <cuda_runtime.h>
#include <cuda_bf16.h>
#include <stdint.h>

#define T_ 12
#define BN_TOT 131072
#define NPRED (BN_TOT * 12)

__device__ __align__(16) uint32_t g_Bh[T_ * 6144];
__device__ __align__(16) uint32_t g_Bx[T_ * 768];
__device__ __align__(16) float g_E2[T_ * 128];

struct Meta { const float *wz, *bz, *Wl[6], *bl[6], *Wb[6], *bb[6], *Wo; };

__device__ __forceinline__ float dot32(const float* a, const float* b) {
    float s = 0.f;
#pragma unroll
    for (int m = 0; m < 32; m++) s = fmaf(a[m], b[m], s);
    return s;
}
__device__ __forceinline__ uint32_t pkbf(float a, float b) {
    return ((uint32_t)__bfloat16_as_ushort(__float2bfloat16(b)) << 16) |
           __bfloat16_as_ushort(__float2bfloat16(a));
}
__device__ __forceinline__ uint32_t pk2(float a, float b) {
    uint32_t d;
    asm("cvt.rn.bf16x2.f32 %0, %1, %2;" : "=r"(d) : "f"(b), "f"(a));
    return d;
}
__device__ __forceinline__ float bf16f(float x) {
    return __bfloat162float(__float2bfloat16(x));
}
__device__ __forceinline__ float tanh_ap(float x) {
    float y;
    asm("tanh.approx.f32 %0, %1;" : "=f"(y) : "f"(x));
    return y;
}

// g_Bh: h-weight fragments (bf16, r/z pre-scaled 0.5): word = t*6144 + (g*8+j)*256 + ks*64 + lane*2 + half
// g_Bx: x/bias fragments, COMPACT 32-word groups: word = t*768 + (g*8+j)*32 + lane (lane<32); by lane%4:
//   q0/q2: {wxhi0, wxhi1}   q1: {bias_hi, bias_lo}   q3: {wxlo0, wxlo1}
// g_E2: per (t,i): {bch, Wo}
__global__ void pre_kernel(Meta p) {
    int idx = blockIdx.x * 256 + threadIdx.x;
    if (idx < 73728) {
        int t = idx / 6144, r = idx % 6144;
        int nt = r / 256, r2 = r % 256;
        int ks = r2 / 64, r3 = r2 % 64;
        int ln = r3 >> 1, half = r3 & 1;
        int n = nt * 8 + (ln >> 2);
        int k0 = ks * 16 + (ln & 3) * 2 + half * 8;
        int g = n >> 6, i = n & 63;
        float gs = (g < 2) ? 0.5f : 1.0f;
        const float* wzt = p.wz + t * 32;
        float s0 = gs * (dot32(wzt, p.Wl[2 * g + 1] + (i * 64 + k0) * 32) + p.bl[2 * g + 1][i * 64 + k0]);
        float s1 = gs * (dot32(wzt, p.Wl[2 * g + 1] + (i * 64 + k0 + 1) * 32) + p.bl[2 * g + 1][i * 64 + k0 + 1]);
        g_Bh[idx] = pkbf(s0, s1);
    } else if (idx < 73728 + 9216) {
        int e = idx - 73728;
        int t = e / 768, r = e % 768;
        int g = r / 256, r2 = r % 256;
        int j = r2 / 32, ln = r2 % 32;
        int q = ln & 3, nn = j * 8 + (ln >> 2);
        float gs = (g < 2) ? 0.5f : 1.0f;
        const float* wzt = p.wz + t * 32;
        uint32_t outw;
        if (q == 1) {
            float b;
            if (g == 0)
                b = 0.5f * (dot32(p.bz + t * 32, p.Wb[0] + nn * 32) + p.bb[0][nn]
                          + dot32(p.bz + t * 32, p.Wb[1] + nn * 32) + p.bb[1][nn]);
            else if (g == 1)
                b = 0.5f * (dot32(p.bz + t * 32, p.Wb[2] + nn * 32) + p.bb[2][nn]
                          + dot32(p.bz + t * 32, p.Wb[3] + nn * 32) + p.bb[3][nn]);
            else
                b = dot32(p.bz + t * 32, p.Wb[4] + nn * 32) + p.bb[4][nn];
            outw = pkbf(b, b - bf16f(b));
        } else {
            float w0 = gs * (dot32(wzt, p.Wl[2 * g] + (nn * 2 + 0) * 32) + p.bl[2 * g][nn * 2 + 0]);
            float w1 = gs * (dot32(wzt, p.Wl[2 * g] + (nn * 2 + 1) * 32) + p.bl[2 * g][nn * 2 + 1]);
            if (q == 3) outw = pkbf(w0 - bf16f(w0), w1 - bf16f(w1));
            else        outw = pkbf(w0, w1);
        }
        g_Bx[e] = outw;
    } else if (idx < 73728 + 9216 + 768) {
        int e = idx - 73728 - 9216;
        int t = e / 64, i = e % 64;
        g_E2[t * 128 + i * 2]     = dot32(p.bz + t * 32, p.Wb[5] + i * 32) + p.bb[5][i];
        g_E2[t * 128 + i * 2 + 1] = p.Wo[i];
    }
}

#define MMA(d, a0_, a1_, a2_, a3_, b0_, b1_) \
    asm volatile("mma.sync.aligned.m16n8k16.row.col.f32.bf16.bf16.f32 " \
        "{%0,%1,%2,%3}, {%4,%5,%6,%7}, {%8,%9}, {%0,%1,%2,%3};" \
        : "+f"((d)[0]), "+f"((d)[1]), "+f"((d)[2]), "+f"((d)[3]) \
        : "r"(a0_), "r"(a1_), "r"(a2_), "r"(a3_), "r"(b0_), "r"(b1_))

#define HF_STRIDE 132          // floats per element row; conflict-free (8q+g4 all distinct)
#define SM_BH0 0
#define SM_BH1 24576
#define SM_BX0 49152
#define SM_BX1 52224
#define SM_X   55296
#define SM_SEQ 68096
#define SM_E20 74240
#define SM_E21 74752
#define SM_WP  75264
#define SM_BP  75840
#define SM_HF  75904
#define SMEM_BYTES (75904 + 64 * HF_STRIDE * 4)   // 75904 + 33792 = 109696 -> 2 CTAs/SM fit

// 256 threads, 8 warps, 16 rows/warp. sHf[e*HF_STRIDE + row] fp32 master h.
__global__ void __launch_bounds__(256, 2)
gru_mma(const float* __restrict__ x, const float* __restrict__ bo,
        const float* __restrict__ Wp, const float* __restrict__ bp,
        float* __restrict__ out, int dup)
{
    extern __shared__ char smem[];
    const int tid = threadIdx.x, lane = tid & 31, wid = tid >> 5;
    const int bn0 = blockIdx.x * 128;
    const int g4 = lane >> 2, q = lane & 3, q2 = q * 2;
    const int r0 = wid * 16 + g4;           // local rows r0, r0+8

    float* sx = (float*)(smem + SM_X);
    float* sSeq = (float*)(smem + SM_SEQ);
    float* sHf = (float*)(smem + SM_HF);
    if (tid < 12) ((float*)(smem + SM_BP))[tid] = bp[tid];
    if (tid < 144) ((float*)(smem + SM_WP))[tid] = Wp[tid];
    if (tid < 128) {
        const float4* gx = (const float4*)x + (size_t)(bn0 + tid) * 6;
#pragma unroll
        for (int u = 0; u < 6; u++) {
            float4 v = gx[u];
            sx[tid * 25 + 4 * u] = v.x; sx[tid * 25 + 4 * u + 1] = v.y;
            sx[tid * 25 + 4 * u + 2] = v.z; sx[tid * 25 + 4 * u + 3] = v.w;
        }
    }
    for (int k = tid; k < 64 * HF_STRIDE; k += 256) sHf[k] = 0.f;
    {   // prologue: stage t=0 into buffer 0
        const uint4* gb = (const uint4*)(g_Bh);
        uint4* db = (uint4*)(smem + SM_BH0);
#pragma unroll
        for (int k = 0; k < 6; k++) db[k * 256 + tid] = gb[k * 256 + tid];
        if (tid < 192) ((uint4*)(smem + SM_BX0))[tid] = ((const uint4*)g_Bx)[tid];
        if (tid < 32) ((uint4*)(smem + SM_E20))[tid] = ((const uint4*)g_E2)[tid];
    }

    uint32_t Ah[4][4];
#pragma unroll
    for (int b = 0; b < 4; b++)
#pragma unroll
        for (int c = 0; c < 4; c++) Ah[b][c] = 0u;
    const float bo0 = __ldg(bo);
    __syncthreads();

    for (int t = 0; t < T_; t++) {
        const uint32_t* sBh = (const uint32_t*)(smem + ((t & 1) ? SM_BH1 : SM_BH0));
        const uint32_t* sBx = (const uint32_t*)(smem + ((t & 1) ? SM_BX1 : SM_BX0));
        const float4* sE2 = (const float4*)(smem + ((t & 1) ? SM_E21 : SM_E20));

        // stage next step into the other buffer
        if (t + 1 < T_) {
            const uint4* gb = (const uint4*)(g_Bh + (t + 1) * 6144);
            uint4* db = (uint4*)(smem + (((t + 1) & 1) ? SM_BH1 : SM_BH0));
#pragma unroll
            for (int k = 0; k < 6; k++) db[k * 256 + tid] = gb[k * 256 + tid];
            if (tid < 192)
                ((uint4*)(smem + (((t + 1) & 1) ? SM_BX1 : SM_BX0)))[tid] =
                    ((const uint4*)(g_Bx + (t + 1) * 768))[tid];
            if (tid < 32)
                ((uint4*)(smem + (((t + 1) & 1) ? SM_E21 : SM_E20)))[tid] =
                    ((const uint4*)(g_E2 + (t + 1) * 128))[tid];
        }

        float oacc[2] = {0.f, 0.f};
        uint32_t ax0, ax1;
        {   // x/bias A fragments for rows r0, r0+8: [xhi, 1/1, xlo, xhi] by quad pos
            float xa0 = sx[r0 * 25 + 2 * t],       xa1 = sx[r0 * 25 + 2 * t + 1];
            float xb0 = sx[(r0 + 8) * 25 + 2 * t], xb1 = sx[(r0 + 8) * 25 + 2 * t + 1];
            if (q == 1) { ax0 = 0x3F803F80u; ax1 = 0x3F803F80u; }
            else if (q == 2) {
                ax0 = pk2(xa0 - bf16f(xa0), xa1 - bf16f(xa1));
                ax1 = pk2(xb0 - bf16f(xb0), xb1 - bf16f(xb1));
            } else {
                ax0 = pk2(bf16f(xa0), bf16f(xa1));
                ax1 = pk2(bf16f(xb0), bf16f(xb1));
            }
        }

#pragma unroll
        for (int j = 0; j < 8; j++) {
            float d[3][4], dxc[4];
#pragma unroll
            for (int a = 0; a < 3; a++)
#pragma unroll
                for (int c = 0; c < 4; c++) d[a][c] = 0.f;
#pragma unroll
            for (int c = 0; c < 4; c++) dxc[c] = 0.f;
#pragma unroll
            for (int ks = 0; ks < 4; ks++) {
#pragma unroll
                for (int g3 = 0; g3 < 3; g3++) {
                    int bi = ((g3 * 8 + j) * 4 + ks) * 64 + lane * 2;
                    uint2 bh = *(const uint2*)(sBh + bi);
                    MMA(d[g3], Ah[ks][0], Ah[ks][1], Ah[ks][2], Ah[ks][3], bh.x, bh.y);
                }
            }
            {   // x-part + bias MMAs (compact 32-word groups)
                uint32_t bxr = sBx[(0 * 8 + j) * 32 + lane];
                uint32_t bxz = sBx[(1 * 8 + j) * 32 + lane];
                uint32_t bxc = sBx[(2 * 8 + j) * 32 + lane];
                MMA(d[0], ax0, ax1, 0u, 0u, bxr, 0u);
                MMA(d[1], ax0, ax1, 0u, 0u, bxz, 0u);
                MMA(dxc, ax0, ax1, 0u, 0u, bxc, 0u);
            }
            int i0 = j * 8 + q2;
            float4 e4 = sE2[i0 >> 1];   // {bch(i0), wo(i0), bch(i0+1), wo(i0+1)}
#pragma unroll
            for (int pp = 0; pp < 2; pp++) {
                int row = r0 + pp * 8;
                float hold0 = sHf[i0 * HF_STRIDE + row];
                float hold1 = sHf[(i0 + 1) * HF_STRIDE + row];

                float tr0 = tanh_ap(d[0][pp * 2]);
                float tz0 = tanh_ap(d[1][pp * 2]);
                float u0 = d[2][pp * 2] + e4.x;
                float c0 = tanh_ap(fmaf(0.5f, fmaf(tr0, u0, u0), dxc[pp * 2]));
                float hn0 = 0.5f * fmaf(tz0, hold0 - c0, hold0 + c0);

                float tr1 = tanh_ap(d[0][pp * 2 + 1]);
                float tz1 = tanh_ap(d[1][pp * 2 + 1]);
                float u1 = d[2][pp * 2 + 1] + e4.z;
                float c1 = tanh_ap(fmaf(0.5f, fmaf(tr1, u1, u1), dxc[pp * 2 + 1]));
                float hn1 = 0.5f * fmaf(tz1, hold1 - c1, hold1 + c1);

                oacc[pp] = fmaf(hn0, e4.y, oacc[pp]);
                oacc[pp] = fmaf(hn1, e4.w, oacc[pp]);
                sHf[i0 * HF_STRIDE + row] = hn0;
                sHf[(i0 + 1) * HF_STRIDE + row] = hn1;
            }
        }
        __syncwarp();   // epilogue writes (all lanes) visible before rebuild reads
        // rebuild A fragments: Ah[ks][c] = h[row(c)][k(c)] pairs, bf16-packed
#pragma unroll
        for (int ks = 0; ks < 4; ks++) {
            int e = ks * 16 + q2;
#pragma unroll
            for (int c = 0; c < 4; c++) {
                int ee = e + (c >> 1) * 8;          // c=2,3 -> k+8
                int row = r0 + (c & 1) * 8;         // c odd -> row+8
                Ah[ks][c] = pk2(sHf[ee * HF_STRIDE + row],
                                sHf[(ee + 1) * HF_STRIDE + row]);
            }
        }
#pragma unroll
        for (int pp = 0; pp < 2; pp++) {
            float v = oacc[pp];
            v += __shfl_xor_sync(0xffffffffu, v, 1);
            v += __shfl_xor_sync(0xffffffffu, v, 2);
            v = fmaxf(v + bo0, 0.f);
            sSeq[t * 128 + r0 + pp * 8] = v;        // quad lanes write same value
        }
        __syncthreads();   // staging of t+1 done + buf[t&1] reads done
    }

    if (tid < 128) {
        const float* sWp = (const float*)(smem + SM_WP);
        const float* sbp = (const float*)(smem + SM_BP);
        float sq[12];
#pragma unroll
        for (int tt = 0; tt < 12; tt++) sq[tt] = sSeq[tt * 128 + tid];
        float pr[12];
#pragma unroll
        for (int p = 0; p < 12; p++) {
            float a = sbp[p];
#pragma unroll
            for (int tt = 0; tt < 12; tt++) a = fmaf(sq[tt], sWp[p * 12 + tt], a);
            pr[p] = a;
        }
        size_t base = (size_t)(bn0 + tid) * 12;
        float4* o4 = (float4*)(out + base);
        o4[0] = make_float4(pr[0], pr[1], pr[2], pr[3]);
        o4[1] = make_float4(pr[4], pr[5], pr[6], pr[7]);
        o4[2] = make_float4(pr[8], pr[9], pr[10], pr[11]);
        if (dup) {
            float4* d4 = (float4*)(out + NPRED + base);
            d4[0] = make_float4(pr[0], pr[1], pr[2], pr[3]);
            d4[1] = make_float4(pr[4], pr[5], pr[6], pr[7]);
            d4[2] = make_float4(pr[8], pr[9], pr[10], pr[11]);
        }
    }
}

extern "C" void kernel_launch(void* const* d_in, const int* in_sizes, int n_in,
                              void* d_out, int out_size) {
    Meta m;
    m.wz = (const float*)d_in[2];
    m.bz = (const float*)d_in[3];
    for (int g = 0; g < 6; g++) {   // rx, rh, zx, zh, cx, ch
        m.Wl[g] = (const float*)d_in[4 + g * 4];
        m.bl[g] = (const float*)d_in[5 + g * 4];
        m.Wb[g] = (const float*)d_in[6 + g * 4];
        m.bb[g] = (const float*)d_in[7 + g * 4];
    }
    m.Wo = (const float*)d_in[28];
    const float* x  = (const float*)d_in[0];
    const float* bo = (const float*)d_in[29];
    const float* Wp = (const float*)d_in[30];
    const float* bp = (const float*)d_in[31];
    float* out = (float*)d_out;

    pre_kernel<<<327, 256>>>(m);

    int dup = (out_size >= 2 * NPRED) ? 1 : 0;
    cudaFuncSetAttribute(gru_mma, cudaFuncAttributeMaxDynamicSharedMemorySize, SMEM_BYTES);
    gru_mma<<<1024, 256, SMEM_BYTES>>>(x, bo, Wp, bp, out, dup);
}